// round 13
// baseline (speedup 1.0000x reference)
#include <cuda_runtime.h>
#include <cuda_fp16.h>
#include <cstdint>

#define B_ROWS 65536
#define D_IN   784
#define DIMZ   128
#define NCLS   10
#define KPROP  64

#define KC      64
#define NCHUNK  13
#define MTILE   64          // rows per CTA

#define A_SCALE 16.0f
#define B_SCALE 1024.0f
#define UNSCALE (1.0f / 16384.0f)

__device__ unsigned char g_Wb[2 * NCHUNK * 16384];   // pre-swizzled fp16 W tiles, 2 split terms

// exact-rounding helpers
__device__ __forceinline__ float MULR(float a, float b) { return __fmul_rn(a, b); }
__device__ __forceinline__ float ADDR(float a, float b) { return __fadd_rn(a, b); }
__device__ __forceinline__ float SUBR(float a, float b) { return __fsub_rn(a, b); }
__device__ __forceinline__ float DIVR(float a, float b) { return __fdiv_rn(a, b); }

__device__ __forceinline__ uint32_t smem_u32(const void* p) {
    uint32_t a;
    asm("{ .reg .u64 t; cvta.to.shared.u64 t, %1; cvt.u32.u64 %0, t; }" : "=r"(a) : "l"(p));
    return a;
}

#define SW128(off) ((off) ^ (((off) >> 3) & 0x70))

__device__ __forceinline__ void cpasync16(uint32_t dst, const void* src) {
    asm volatile("cp.async.cg.shared.global [%0], [%1], 16;" :: "r"(dst), "l"(src));
}
#define CPCOMMIT() asm volatile("cp.async.commit_group;")
#define CPWAIT0()  asm volatile("cp.async.wait_group 0;")

// ---------------- JAX Threefry-2x32 (20 rounds), partitionable mode ----------------
struct K2 { uint32_t a, b; };

__device__ __forceinline__ void tf2x32(uint32_t k0, uint32_t k1, uint32_t c0, uint32_t c1,
                                       uint32_t &o0, uint32_t &o1) {
    uint32_t ks2 = k0 ^ k1 ^ 0x1BD11BDAu;
    uint32_t x0 = c0 + k0;
    uint32_t x1 = c1 + k1;
#define TFR(r) { x0 += x1; x1 = __funnelshift_l(x1, x1, (r)); x1 ^= x0; }
    TFR(13) TFR(15) TFR(26) TFR(6)
    x0 += k1;  x1 += ks2 + 1u;
    TFR(17) TFR(29) TFR(16) TFR(24)
    x0 += ks2; x1 += k0 + 2u;
    TFR(13) TFR(15) TFR(26) TFR(6)
    x0 += k0;  x1 += k1 + 3u;
    TFR(17) TFR(29) TFR(16) TFR(24)
    x0 += k1;  x1 += ks2 + 4u;
    TFR(13) TFR(15) TFR(26) TFR(6)
    x0 += ks2; x1 += k0 + 5u;
#undef TFR
    o0 = x0; o1 = x1;
}

__device__ __forceinline__ K2 keyderive(K2 k, uint32_t hi, uint32_t lo) {
    K2 r; tf2x32(k.a, k.b, hi, lo, r.a, r.b); return r;
}
__device__ __forceinline__ uint32_t bits32(K2 k, uint32_t hi, uint32_t lo) {
    uint32_t a, b; tf2x32(k.a, k.b, hi, lo, a, b); return a ^ b;
}
__device__ __forceinline__ float u01_from_bits(uint32_t bits) {
    return SUBR(__uint_as_float((bits >> 9) | 0x3f800000u), 1.0f);   // [0,1)
}
__device__ __forceinline__ float uniform01(K2 k) { return u01_from_bits(bits32(k, 0u, 0u)); }

// XLA ErfInv f32 (Giles), un-contracted
__device__ __forceinline__ float erfinv_xla(float x) {
    float w = -log1pf(-MULR(x, x));
    float p;
    if (w < 5.0f) {
        w = SUBR(w, 2.5f);
        p = 2.81022636e-08f;
        p = ADDR(MULR(p, w), 3.43273939e-07f);
        p = ADDR(MULR(p, w), -3.5233877e-06f);
        p = ADDR(MULR(p, w), -4.39150654e-06f);
        p = ADDR(MULR(p, w), 0.00021858087f);
        p = ADDR(MULR(p, w), -0.00125372503f);
        p = ADDR(MULR(p, w), -0.00417768164f);
        p = ADDR(MULR(p, w), 0.246640727f);
        p = ADDR(MULR(p, w), 1.50140941f);
    } else {
        w = SUBR(sqrtf(w), 3.0f);
        p = -0.000200214257f;
        p = ADDR(MULR(p, w), 0.000100950558f);
        p = ADDR(MULR(p, w), 0.00134934322f);
        p = ADDR(MULR(p, w), -0.00367342844f);
        p = ADDR(MULR(p, w), 0.00573950773f);
        p = ADDR(MULR(p, w), -0.0076224613f);
        p = ADDR(MULR(p, w), 0.00943887047f);
        p = ADDR(MULR(p, w), 1.00167406f);
        p = ADDR(MULR(p, w), 2.83297682f);
    }
    return MULR(p, x);
}

__device__ __forceinline__ float normal_from_bits(uint32_t bits) {
    const float LO = -0.99999994f;
    float f = u01_from_bits(bits);
    float val = fmaxf(LO, ADDR(MULR(f, 2.0f), LO));
    return MULR(1.41421356237309515f, erfinv_xla(val));
}
__device__ __forceinline__ float normal_scalar(K2 k) { return normal_from_bits(bits32(k, 0u, 0u)); }

// jax._src.random._gamma_one, log_space=True, alpha=63.5
__device__ float loggamma_a635(K2 key_elem) {
    const float d = SUBR(63.5f, 0.33333334f);
    const float c = DIVR(0.33333334f, sqrtf(d));
    K2 key = keyderive(key_elem, 0u, 0u);
    float V = 1.0f;
    for (int it = 0; it < 64; ++it) {
        K2 nkey = keyderive(key, 0u, 0u);
        K2 xkey = keyderive(key, 0u, 1u);
        K2 Ukey = keyderive(key, 0u, 2u);
        key = nkey;
        float x = 0.0f, v = -1.0f;
        for (int j = 0; j < 8; ++j) {
            K2 sub = keyderive(xkey, 0u, 1u);
            x = normal_scalar(sub);
            v = ADDR(1.0f, MULR(x, c));
            if (v > 0.0f) break;
            xkey = keyderive(xkey, 0u, 0u);
        }
        float X = MULR(x, x);
        V = MULR(MULR(v, v), v);
        float U = uniform01(Ukey);
        if (U < SUBR(1.0f, MULR(0.0331f, MULR(X, X)))) break;
        if (logf(U) < ADDR(MULR(X, 0.5f), MULR(d, ADDR(SUBR(1.0f, V), logf(V))))) break;
    }
    return ADDR(logf(d), logf(V));
}

__device__ __forceinline__ float beta_e(K2 kA, K2 kB) {
    float la = loggamma_a635(kA);
    float lb = loggamma_a635(kB);
    float mx = fmaxf(la, lb);
    float ea = expf(SUBR(la, mx));
    float eb = expf(SUBR(lb, mx));
    return DIVR(ea, ADDR(ea, eb));
}

__device__ __forceinline__ void cvt2(float xs, __half &h0, __half &h1) {
    h0 = __float2half_rn(xs);
    h1 = __float2half_rn(xs - __half2float(h0));
}

// ---------------- kernel 0: pre-convert W into swizzled fp16 term tiles (x1024) ----------------
__global__ __launch_bounds__(256) void convw_kernel(const float* __restrict__ W) {
    int idx = blockIdx.x * 256 + threadIdx.x;
    if (idx >= 104 * 128) return;
    int n = idx & 127;
    int kg = idx >> 7;
    int k0 = kg * 8;
    union { __half h[8]; uint4 v; } u0, u1;
#pragma unroll
    for (int e = 0; e < 8; e++) {
        int k = k0 + e;
        float wv = (k < D_IN) ? W[k * DIMZ + n] * B_SCALE : 0.0f;
        cvt2(wv, u0.h[e], u1.h[e]);
    }
    int chunk = k0 >> 6;
    int kin = k0 & 63;
    uint32_t off = (uint32_t)chunk * 16384u + SW128((uint32_t)(n * 128 + kin * 2));
    *(uint4*)&g_Wb[0 * NCHUNK * 16384 + off] = u0.v;
    *(uint4*)&g_Wb[1 * NCHUNK * 16384 + off] = u1.v;
}

// ===== fused: GEMM (fp16 2x2 split, HMMA) + mu/kappa + sampler + finish, M-tile 64 =====
static constexpr int OFF_BIAS  = 0;
static constexpr int OFF_WVAR  = 512;
static constexpr int OFF_WDEC  = 1024;                   // 1280 f
static constexpr int OFF_KAP   = 6272;                   // 64 f
static constexpr int OFF_W     = 6528;                   // 64 f
static constexpr int OFF_A     = 8192;                   // 2 stages x 2 terms x 8KB
static constexpr int OFF_B     = OFF_A + 4 * 8192;       // 2 stages x 2 terms x 16KB
static constexpr int SMEM_ENC  = OFF_B + 4 * 16384;      // ~104KB -> 2 CTAs/SM
static constexpr int OFF_H     = OFF_A;
static constexpr int HSTRIDE   = 132;

__device__ __forceinline__ void ldm_x4(uint32_t &r0, uint32_t &r1, uint32_t &r2, uint32_t &r3,
                                       uint32_t addr) {
    asm volatile("ldmatrix.sync.aligned.m8n8.x4.shared.b16 {%0,%1,%2,%3}, [%4];"
                 : "=r"(r0), "=r"(r1), "=r"(r2), "=r"(r3) : "r"(addr));
}
__device__ __forceinline__ void mma_f16(float* c, const uint32_t* a, const uint32_t* b) {
    asm volatile(
        "mma.sync.aligned.m16n8k16.row.col.f32.f16.f16.f32 "
        "{%0,%1,%2,%3}, {%4,%5,%6,%7}, {%8,%9}, {%0,%1,%2,%3};"
        : "+f"(c[0]), "+f"(c[1]), "+f"(c[2]), "+f"(c[3])
        : "r"(a[0]), "r"(a[1]), "r"(a[2]), "r"(a[3]), "r"(b[0]), "r"(b[1]));
}
__device__ __forceinline__ float warpAllSum(float v) {
#pragma unroll
    for (int o = 16; o > 0; o >>= 1) v += __shfl_xor_sync(0xffffffffu, v, o);
    return v;
}

__global__ __launch_bounds__(256, 2)
void fused_kernel(const float* __restrict__ X,
                  const float* __restrict__ bias,
                  const float* __restrict__ Wvar,
                  const float* __restrict__ bvar,
                  const float* __restrict__ Wdec,
                  const float* __restrict__ bdec,
                  float* __restrict__ out) {
    extern __shared__ __align__(16) char smem[];
    const uint32_t sb = smem_u32(smem);
    const int tid = threadIdx.x;
    const int rowBase = blockIdx.x * MTILE;

    float* sbias = (float*)(smem + OFF_BIAS);
    float* swvar = (float*)(smem + OFF_WVAR);
    float* swdec = (float*)(smem + OFF_WDEC);
    float* skap  = (float*)(smem + OFF_KAP);
    float* sw    = (float*)(smem + OFF_W);
    if (tid < 128) { sbias[tid] = bias[tid]; swvar[tid] = Wvar[tid]; }
    for (int i = tid; i < DIMZ * NCLS; i += 256) swdec[i] = Wdec[i];

    const int wid = tid >> 5, lane = tid & 31;
    const int mrow = (wid & 1) * 32;
    const int ncol = (wid >> 1) * 32;

    float acc[2][4][4];
#pragma unroll
    for (int mt = 0; mt < 2; mt++)
#pragma unroll
        for (int nt = 0; nt < 4; nt++)
#pragma unroll
            for (int e = 0; e < 4; e++) acc[mt][nt][e] = 0.0f;

    const int rowA = lane & 15;
    const int colA = (lane >> 4) * 8;
    const int nB   = ((lane >> 4) << 3) + (lane & 7);
    const int kB   = ((lane >> 3) & 1) * 8;

    const int cr  = tid >> 2;
    const int ck0 = (tid & 3) * 16;

    auto loadX = [&](float* xv, int t) {
        int k0 = t * KC;
        if (k0 + ck0 + 16 <= D_IN) {
            const float4* p = (const float4*)&X[(rowBase + cr) * D_IN + k0 + ck0];
#pragma unroll
            for (int q = 0; q < 4; q++) {
                float4 v = p[q];
                xv[q * 4 + 0] = v.x; xv[q * 4 + 1] = v.y;
                xv[q * 4 + 2] = v.z; xv[q * 4 + 3] = v.w;
            }
        } else {
#pragma unroll
            for (int e = 0; e < 16; e++) xv[e] = 0.0f;
        }
    };
    auto storeA = [&](int st, const float* xv) {
        union { __half h[16]; uint4 v[2]; } u0, u1;
#pragma unroll
        for (int e = 0; e < 16; e++) cvt2(xv[e] * A_SCALE, u0.h[e], u1.h[e]);
        uint32_t o0 = SW128((uint32_t)(cr * 128 + ck0 * 2));
        uint32_t o1 = SW128((uint32_t)(cr * 128 + ck0 * 2 + 16));
        char* base = smem + OFF_A + st * 2 * 8192;
        *(uint4*)(base + o0)            = u0.v[0];
        *(uint4*)(base + o1)            = u0.v[1];
        *(uint4*)(base + 8192 + o0)     = u1.v[0];
        *(uint4*)(base + 8192 + o1)     = u1.v[1];
    };
    auto loadB = [&](int st, int t) {
        const unsigned char* src = g_Wb + (size_t)t * 16384 + tid * 64;
#pragma unroll
        for (int term = 0; term < 2; term++) {
            uint32_t d = sb + OFF_B + (st * 2 + term) * 16384 + tid * 64;
            const unsigned char* s = src + (size_t)term * NCHUNK * 16384;
#pragma unroll
            for (int q = 0; q < 4; q++) cpasync16(d + q * 16, s + q * 16);
        }
    };

    float xv[16];
    {   // prologue
        loadB(0, 0);
        CPCOMMIT();
        loadX(xv, 0);
        storeA(0, xv);
        CPWAIT0();
    }
    __syncthreads();

    for (int t = 0; t < NCHUNK; ++t) {
        const int cur = t & 1, nxt = cur ^ 1;
        const bool hasNext = (t + 1 < NCHUNK);
        if (hasNext) {
            loadB(nxt, t + 1);
            CPCOMMIT();
            loadX(xv, t + 1);
        }
#pragma unroll
        for (int ks = 0; ks < 4; ++ks) {
            uint32_t bfr[2][4][2];
#pragma unroll
            for (int bt = 0; bt < 2; bt++) {
#pragma unroll
                for (int np = 0; np < 2; np++) {
                    uint32_t addr = sb + OFF_B + (cur * 2 + bt) * 16384 +
                        SW128((uint32_t)((ncol + np * 16 + nB) * 128 + (ks * 16 + kB) * 2));
                    ldm_x4(bfr[bt][2 * np][0], bfr[bt][2 * np][1],
                           bfr[bt][2 * np + 1][0], bfr[bt][2 * np + 1][1], addr);
                }
            }
#pragma unroll
            for (int at = 0; at < 2; at++) {
                uint32_t afr[2][4];
#pragma unroll
                for (int mt = 0; mt < 2; mt++) {
                    uint32_t addr = sb + OFF_A + (cur * 2 + at) * 8192 +
                        SW128((uint32_t)((mrow + mt * 16 + rowA) * 128 + (ks * 16 + colA) * 2));
                    ldm_x4(afr[mt][0], afr[mt][1], afr[mt][2], afr[mt][3], addr);
                }
#pragma unroll
                for (int bt = 0; bt < 2; bt++) {
#pragma unroll
                    for (int mt = 0; mt < 2; mt++)
#pragma unroll
                        for (int nt = 0; nt < 4; nt++)
                            mma_f16(acc[mt][nt], afr[mt], bfr[bt][nt]);
                }
            }
            // overlap next-stage convert+STS with the final k-step's MMAs
            if (ks == 2 && hasNext) storeA(nxt, xv);
        }
        if (hasNext) CPWAIT0();
        __syncthreads();
    }

    // ---- epilogue 1: acc*2^-14 + bias -> hbuf ----
    float* hbuf = (float*)(smem + OFF_H);
    {
        int rr = lane >> 2, cc = (lane & 3) * 2;
#pragma unroll
        for (int mt = 0; mt < 2; mt++)
#pragma unroll
            for (int nt = 0; nt < 4; nt++) {
                int r0 = mrow + mt * 16 + rr;
                int c0 = ncol + nt * 8 + cc;
                hbuf[r0 * HSTRIDE + c0]           = acc[mt][nt][0] * UNSCALE + sbias[c0];
                hbuf[r0 * HSTRIDE + c0 + 1]       = acc[mt][nt][1] * UNSCALE + sbias[c0 + 1];
                hbuf[(r0 + 8) * HSTRIDE + c0]     = acc[mt][nt][2] * UNSCALE + sbias[c0];
                hbuf[(r0 + 8) * HSTRIDE + c0 + 1] = acc[mt][nt][3] * UNSCALE + sbias[c0 + 1];
            }
    }
    __syncthreads();

    // ---- epilogue 2: mu (in-place) + kappa ----
    {
        int row = tid >> 2, q = tid & 3;
        float* hrow = &hbuf[row * HSTRIDE + q * 32];
        float nrm = 0.0f, kp = 0.0f;
#pragma unroll
        for (int c = 0; c < 32; c++) {
            float hv = hrow[c];
            nrm = fmaf(hv, hv, nrm);
            kp  = fmaf(hv, swvar[q * 32 + c], kp);
        }
        nrm += __shfl_xor_sync(0xffffffffu, nrm, 1);
        nrm += __shfl_xor_sync(0xffffffffu, nrm, 2);
        kp  += __shfl_xor_sync(0xffffffffu, kp, 1);
        kp  += __shfl_xor_sync(0xffffffffu, kp, 2);
        float rinv = 1.0f / (sqrtf(nrm) + 1e-8f);
#pragma unroll
        for (int c = 0; c < 32; c++) hrow[c] *= rinv;    // hbuf now holds mu
        if (q == 0) {
            float xv2 = kp + bvar[0];
            float sp = fmaxf(xv2, 0.0f) + log1pf(expf(-fabsf(xv2)));
            skap[row] = sp + 1.0f;
        }
    }
    __syncthreads();

    // ---- phase 3: 4-way parallel lazy vMF rejection sampler (4 threads per row) ----
    {
        int row  = tid >> 2, q = tid & 3;
        int grow = rowBase + row;
        K2 root; root.a = 0u; root.b = 42u;
        K2 ke   = keyderive(root, 0u, 0u);
        K2 ku   = keyderive(root, 0u, 1u);
        K2 keyA = keyderive(ke, 0u, 0u);
        K2 keyB = keyderive(ke, 0u, 1u);

        float kap = skap[row];
        float c  = sqrtf(ADDR(MULR(4.0f, MULR(kap, kap)), 16129.0f));
        float bt = DIVR(ADDR(MULR(-2.0f, kap), c), 127.0f);
        float ba = DIVR(127.0f, MULR(4.0f, kap));
        float s  = fminf(fmaxf(SUBR(kap, 10.0f), 0.0f), 1.0f);
        float bb = ADDR(MULR(ba, s), MULR(bt, SUBR(1.0f, s)));
        float aa = DIVR(ADDR(ADDR(127.0f, MULR(2.0f, kap)), c), 4.0f);
        float dd = SUBR(DIVR(MULR(MULR(4.0f, aa), bb), ADDR(1.0f, bb)),
                        MULR(127.0f, (float)4.844187086458591));

        bool done = false;
        float wsel = 0.0f;
        for (int round = 0; round < 16; ++round) {
            if (!__ballot_sync(0xffffffffu, !done)) break;   // warp-uniform early exit
            uint32_t k = (uint32_t)round * 4u + (uint32_t)q;
            float wk = 0.0f;
            uint32_t aflag = 4u;                             // 4 = not accepted
            if (!done) {
                uint32_t i = (uint32_t)grow * 64u + k;
                float e = beta_e(keyderive(keyA, 0u, i), keyderive(keyB, 0u, i));
                float denom = SUBR(1.0f, MULR(SUBR(1.0f, bb), e));
                wk = DIVR(SUBR(1.0f, MULR(ADDR(1.0f, bb), e)), denom);
                float tt = DIVR(MULR(MULR(2.0f, aa), bb), denom);
                float uf = fmaxf(1e-20f, ADDR(u01_from_bits(bits32(ku, 0u, i)), 1e-20f));
                float lhs = ADDR(SUBR(MULR(127.0f, logf(tt)), tt), dd);
                if (lhs > logf(uf)) aflag = (uint32_t)q;
            }
            uint32_t m1 = min(aflag, __shfl_xor_sync(0xffffffffu, aflag, 1));
            uint32_t m2 = min(m1,   __shfl_xor_sync(0xffffffffu, m1, 2));
            int srcq = (m2 < 4u) ? (int)m2 : 3;              // fallback: q=3 holds k=63 on round 15
            float wWin = __shfl_sync(0xffffffffu, wk, (lane & ~3) | srcq);
            if (!done) {
                if (m2 < 4u)            { wsel = wWin; done = true; }
                else if (round == 15)   { wsel = wWin; done = true; }
            }
        }
        if (q == 0) sw[row] = wsel;
    }
    __syncthreads();

    // ---- phase 4: tangent normals + Householder + decoder (warp per row, 8 iters) ----
    K2 root; root.a = 0u; root.b = 42u;
    K2 kv = keyderive(root, 0u, 2u);
    for (int r8 = 0; r8 < 8; r8++) {
        int rloc = r8 * 8 + wid;
        int grow = rowBase + rloc;
        const float* mrowp = &hbuf[rloc * HSTRIDE];
        float mu[4];
#pragma unroll
        for (int q = 0; q < 4; q++) mu[q] = mrowp[lane * 4 + q];

        float v[4];
        float vs = 0.0f;
#pragma unroll
        for (int q = 0; q < 4; q++) {
            int j = lane * 4 + q;
            v[q] = 0.0f;
            if (j >= 1)
                v[q] = normal_from_bits(bits32(kv, 0u, (uint32_t)grow * 127u + (uint32_t)(j - 1)));
            vs = fmaf(v[q], v[q], vs);
        }
        vs = warpAllSum(vs);
        float vninv = 1.0f / sqrtf(vs);

        float w = sw[rloc];
        float wperp = sqrtf(fmaxf(1.0f - w * w, 1e-10f));

        float x[4], uh[4];
        float un = 0.0f;
#pragma unroll
        for (int q = 0; q < 4; q++) {
            int j = lane * 4 + q;
            x[q]  = (j == 0) ? w : wperp * (v[q] * vninv);
            uh[q] = ((j == 0) ? 1.0f : 0.0f) - mu[q];
            un = fmaf(uh[q], uh[q], un);
        }
        un = warpAllSum(un);
        float uinv = 1.0f / (sqrtf(un) + 1e-5f);

        float xd = 0.0f;
#pragma unroll
        for (int q = 0; q < 4; q++) { uh[q] *= uinv; xd = fmaf(x[q], uh[q], xd); }
        xd = warpAllSum(xd);

        float z[4];
#pragma unroll
        for (int q = 0; q < 4; q++) z[q] = x[q] - 2.0f * xd * uh[q];

        float dacc[NCLS];
#pragma unroll
        for (int c = 0; c < NCLS; c++) dacc[c] = 0.0f;
#pragma unroll
        for (int q = 0; q < 4; q++) {
            int r = lane * 4 + q;
#pragma unroll
            for (int c = 0; c < NCLS; c++) dacc[c] = fmaf(z[q], swdec[r * NCLS + c], dacc[c]);
        }
#pragma unroll
        for (int c = 0; c < NCLS; c++) {
            dacc[c] = warpAllSum(dacc[c]);
            if (lane == c) out[grow * NCLS + c] = dacc[c] + bdec[c];
        }
    }
}

extern "C" void kernel_launch(void* const* d_in, const int* in_sizes, int n_in,
                              void* d_out, int out_size) {
    const float* x    = (const float*)d_in[0];
    const float* Wenc = (const float*)d_in[1];
    const float* benc = (const float*)d_in[2];
    const float* Wvar = (const float*)d_in[3];
    const float* bvar = (const float*)d_in[4];
    const float* Wdec = (const float*)d_in[5];
    const float* bdec = (const float*)d_in[6];
    float* out = (float*)d_out;

    cudaFuncSetAttribute(fused_kernel, cudaFuncAttributeMaxDynamicSharedMemorySize, SMEM_ENC);
    convw_kernel<<<(104 * 128 + 255) / 256, 256>>>(Wenc);
    fused_kernel<<<B_ROWS / MTILE, 256, SMEM_ENC>>>(x, benc, Wvar, bvar, Wdec, bdec, out);
}

// round 14
// speedup vs baseline: 1.0637x; 1.0637x over previous
#include <cuda_runtime.h>
#include <cuda_fp16.h>
#include <cstdint>

#define B_ROWS 65536
#define D_IN   784
#define DIMZ   128
#define NCLS   10
#define KPROP  64

#define KC      64
#define NCHUNK  13
#define MTILE   64          // rows per CTA

#define A_SCALE 16.0f
#define B_SCALE 1024.0f
#define UNSCALE (1.0f / 16384.0f)

__device__ unsigned char g_Wb[2 * NCHUNK * 16384];   // pre-swizzled fp16 W tiles, 2 split terms

// exact-rounding helpers
__device__ __forceinline__ float MULR(float a, float b) { return __fmul_rn(a, b); }
__device__ __forceinline__ float ADDR(float a, float b) { return __fadd_rn(a, b); }
__device__ __forceinline__ float SUBR(float a, float b) { return __fsub_rn(a, b); }
__device__ __forceinline__ float DIVR(float a, float b) { return __fdiv_rn(a, b); }

__device__ __forceinline__ uint32_t smem_u32(const void* p) {
    uint32_t a;
    asm("{ .reg .u64 t; cvta.to.shared.u64 t, %1; cvt.u32.u64 %0, t; }" : "=r"(a) : "l"(p));
    return a;
}

#define SW128(off) ((off) ^ (((off) >> 3) & 0x70))

__device__ __forceinline__ void cpasync16(uint32_t dst, const void* src) {
    asm volatile("cp.async.cg.shared.global [%0], [%1], 16;" :: "r"(dst), "l"(src));
}
#define CPCOMMIT() asm volatile("cp.async.commit_group;")
#define CPWAIT0()  asm volatile("cp.async.wait_group 0;")

// ---------------- JAX Threefry-2x32 (20 rounds), partitionable mode ----------------
struct K2 { uint32_t a, b; };

__device__ __forceinline__ void tf2x32(uint32_t k0, uint32_t k1, uint32_t c0, uint32_t c1,
                                       uint32_t &o0, uint32_t &o1) {
    uint32_t ks2 = k0 ^ k1 ^ 0x1BD11BDAu;
    uint32_t x0 = c0 + k0;
    uint32_t x1 = c1 + k1;
#define TFR(r) { x0 += x1; x1 = __funnelshift_l(x1, x1, (r)); x1 ^= x0; }
    TFR(13) TFR(15) TFR(26) TFR(6)
    x0 += k1;  x1 += ks2 + 1u;
    TFR(17) TFR(29) TFR(16) TFR(24)
    x0 += ks2; x1 += k0 + 2u;
    TFR(13) TFR(15) TFR(26) TFR(6)
    x0 += k0;  x1 += k1 + 3u;
    TFR(17) TFR(29) TFR(16) TFR(24)
    x0 += k1;  x1 += ks2 + 4u;
    TFR(13) TFR(15) TFR(26) TFR(6)
    x0 += ks2; x1 += k0 + 5u;
#undef TFR
    o0 = x0; o1 = x1;
}

__device__ __forceinline__ K2 keyderive(K2 k, uint32_t hi, uint32_t lo) {
    K2 r; tf2x32(k.a, k.b, hi, lo, r.a, r.b); return r;
}
__device__ __forceinline__ uint32_t bits32(K2 k, uint32_t hi, uint32_t lo) {
    uint32_t a, b; tf2x32(k.a, k.b, hi, lo, a, b); return a ^ b;
}
__device__ __forceinline__ float u01_from_bits(uint32_t bits) {
    return SUBR(__uint_as_float((bits >> 9) | 0x3f800000u), 1.0f);   // [0,1)
}
__device__ __forceinline__ float uniform01(K2 k) { return u01_from_bits(bits32(k, 0u, 0u)); }

// XLA ErfInv f32 (Giles), un-contracted
__device__ __forceinline__ float erfinv_xla(float x) {
    float w = -log1pf(-MULR(x, x));
    float p;
    if (w < 5.0f) {
        w = SUBR(w, 2.5f);
        p = 2.81022636e-08f;
        p = ADDR(MULR(p, w), 3.43273939e-07f);
        p = ADDR(MULR(p, w), -3.5233877e-06f);
        p = ADDR(MULR(p, w), -4.39150654e-06f);
        p = ADDR(MULR(p, w), 0.00021858087f);
        p = ADDR(MULR(p, w), -0.00125372503f);
        p = ADDR(MULR(p, w), -0.00417768164f);
        p = ADDR(MULR(p, w), 0.246640727f);
        p = ADDR(MULR(p, w), 1.50140941f);
    } else {
        w = SUBR(sqrtf(w), 3.0f);
        p = -0.000200214257f;
        p = ADDR(MULR(p, w), 0.000100950558f);
        p = ADDR(MULR(p, w), 0.00134934322f);
        p = ADDR(MULR(p, w), -0.00367342844f);
        p = ADDR(MULR(p, w), 0.00573950773f);
        p = ADDR(MULR(p, w), -0.0076224613f);
        p = ADDR(MULR(p, w), 0.00943887047f);
        p = ADDR(MULR(p, w), 1.00167406f);
        p = ADDR(MULR(p, w), 2.83297682f);
    }
    return MULR(p, x);
}

__device__ __forceinline__ float normal_from_bits(uint32_t bits) {
    const float LO = -0.99999994f;
    float f = u01_from_bits(bits);
    float val = fmaxf(LO, ADDR(MULR(f, 2.0f), LO));
    return MULR(1.41421356237309515f, erfinv_xla(val));
}
__device__ __forceinline__ float normal_scalar(K2 k) { return normal_from_bits(bits32(k, 0u, 0u)); }

// jax._src.random._gamma_one, log_space=True, alpha=63.5
__device__ float loggamma_a635(K2 key_elem) {
    const float d = SUBR(63.5f, 0.33333334f);
    const float c = DIVR(0.33333334f, sqrtf(d));
    K2 key = keyderive(key_elem, 0u, 0u);
    float V = 1.0f;
    for (int it = 0; it < 64; ++it) {
        K2 nkey = keyderive(key, 0u, 0u);
        K2 xkey = keyderive(key, 0u, 1u);
        K2 Ukey = keyderive(key, 0u, 2u);
        key = nkey;
        float x = 0.0f, v = -1.0f;
        for (int j = 0; j < 8; ++j) {
            K2 sub = keyderive(xkey, 0u, 1u);
            x = normal_scalar(sub);
            v = ADDR(1.0f, MULR(x, c));
            if (v > 0.0f) break;
            xkey = keyderive(xkey, 0u, 0u);
        }
        float X = MULR(x, x);
        V = MULR(MULR(v, v), v);
        float U = uniform01(Ukey);
        if (U < SUBR(1.0f, MULR(0.0331f, MULR(X, X)))) break;
        if (logf(U) < ADDR(MULR(X, 0.5f), MULR(d, ADDR(SUBR(1.0f, V), logf(V))))) break;
    }
    return ADDR(logf(d), logf(V));
}

__device__ __forceinline__ float beta_e(K2 kA, K2 kB) {
    float la = loggamma_a635(kA);
    float lb = loggamma_a635(kB);
    float mx = fmaxf(la, lb);
    float ea = expf(SUBR(la, mx));
    float eb = expf(SUBR(lb, mx));
    return DIVR(ea, ADDR(ea, eb));
}

__device__ __forceinline__ void cvt2(float xs, __half &h0, __half &h1) {
    h0 = __float2half_rn(xs);
    h1 = __float2half_rn(xs - __half2float(h0));
}

// ---------------- kernel 0: pre-convert W into swizzled fp16 term tiles (x1024) ----------------
__global__ __launch_bounds__(256) void convw_kernel(const float* __restrict__ W) {
    int idx = blockIdx.x * 256 + threadIdx.x;
    if (idx >= 104 * 128) return;
    int n = idx & 127;
    int kg = idx >> 7;
    int k0 = kg * 8;
    union { __half h[8]; uint4 v; } u0, u1;
#pragma unroll
    for (int e = 0; e < 8; e++) {
        int k = k0 + e;
        float wv = (k < D_IN) ? W[k * DIMZ + n] * B_SCALE : 0.0f;
        cvt2(wv, u0.h[e], u1.h[e]);
    }
    int chunk = k0 >> 6;
    int kin = k0 & 63;
    uint32_t off = (uint32_t)chunk * 16384u + SW128((uint32_t)(n * 128 + kin * 2));
    *(uint4*)&g_Wb[0 * NCHUNK * 16384 + off] = u0.v;
    *(uint4*)&g_Wb[1 * NCHUNK * 16384 + off] = u1.v;
}

// ===== fused: GEMM (fp16 split, 3 products, HMMA) + mu/kappa + sampler + finish =====
static constexpr int OFF_BIAS  = 0;
static constexpr int OFF_WVAR  = 512;
static constexpr int OFF_WDEC  = 1024;                   // 1280 f
static constexpr int OFF_KAP   = 6272;                   // 64 f
static constexpr int OFF_W     = 6528;                   // 64 f
static constexpr int OFF_A     = 8192;                   // 2 stages x 2 terms x 8KB
static constexpr int OFF_B     = OFF_A + 4 * 8192;       // 2 stages x 2 terms x 16KB
static constexpr int SMEM_ENC  = OFF_B + 4 * 16384;      // ~104KB -> 2 CTAs/SM
static constexpr int OFF_H     = OFF_A;
static constexpr int HSTRIDE   = 132;

__device__ __forceinline__ void ldm_x4(uint32_t &r0, uint32_t &r1, uint32_t &r2, uint32_t &r3,
                                       uint32_t addr) {
    asm volatile("ldmatrix.sync.aligned.m8n8.x4.shared.b16 {%0,%1,%2,%3}, [%4];"
                 : "=r"(r0), "=r"(r1), "=r"(r2), "=r"(r3) : "r"(addr));
}
__device__ __forceinline__ void mma_f16(float* c, const uint32_t* a, const uint32_t* b) {
    asm volatile(
        "mma.sync.aligned.m16n8k16.row.col.f32.f16.f16.f32 "
        "{%0,%1,%2,%3}, {%4,%5,%6,%7}, {%8,%9}, {%0,%1,%2,%3};"
        : "+f"(c[0]), "+f"(c[1]), "+f"(c[2]), "+f"(c[3])
        : "r"(a[0]), "r"(a[1]), "r"(a[2]), "r"(a[3]), "r"(b[0]), "r"(b[1]));
}
__device__ __forceinline__ float warpAllSum(float v) {
#pragma unroll
    for (int o = 16; o > 0; o >>= 1) v += __shfl_xor_sync(0xffffffffu, v, o);
    return v;
}

__global__ __launch_bounds__(256, 2)
void fused_kernel(const float* __restrict__ X,
                  const float* __restrict__ bias,
                  const float* __restrict__ Wvar,
                  const float* __restrict__ bvar,
                  const float* __restrict__ Wdec,
                  const float* __restrict__ bdec,
                  float* __restrict__ out) {
    extern __shared__ __align__(16) char smem[];
    const uint32_t sb = smem_u32(smem);
    const int tid = threadIdx.x;
    const int rowBase = blockIdx.x * MTILE;

    float* sbias = (float*)(smem + OFF_BIAS);
    float* swvar = (float*)(smem + OFF_WVAR);
    float* swdec = (float*)(smem + OFF_WDEC);
    float* skap  = (float*)(smem + OFF_KAP);
    float* sw    = (float*)(smem + OFF_W);
    if (tid < 128) { sbias[tid] = bias[tid]; swvar[tid] = Wvar[tid]; }
    for (int i = tid; i < DIMZ * NCLS; i += 256) swdec[i] = Wdec[i];

    const int wid = tid >> 5, lane = tid & 31;
    const int mrow = (wid & 1) * 32;
    const int ncol = (wid >> 1) * 32;

    float acc[2][4][4];
#pragma unroll
    for (int mt = 0; mt < 2; mt++)
#pragma unroll
        for (int nt = 0; nt < 4; nt++)
#pragma unroll
            for (int e = 0; e < 4; e++) acc[mt][nt][e] = 0.0f;

    const int rowA = lane & 15;
    const int colA = (lane >> 4) * 8;
    const int nB   = ((lane >> 4) << 3) + (lane & 7);
    const int kB   = ((lane >> 3) & 1) * 8;

    const int cr  = tid >> 2;
    const int ck0 = (tid & 3) * 16;

    auto loadX = [&](float* xv, int t) {
        int k0 = t * KC;
        if (k0 + ck0 + 16 <= D_IN) {
            const float4* p = (const float4*)&X[(rowBase + cr) * D_IN + k0 + ck0];
#pragma unroll
            for (int q = 0; q < 4; q++) {
                float4 v = p[q];
                xv[q * 4 + 0] = v.x; xv[q * 4 + 1] = v.y;
                xv[q * 4 + 2] = v.z; xv[q * 4 + 3] = v.w;
            }
        } else {
#pragma unroll
            for (int e = 0; e < 16; e++) xv[e] = 0.0f;
        }
    };
    auto storeA = [&](int st, const float* xv) {
        union { __half h[16]; uint4 v[2]; } u0, u1;
#pragma unroll
        for (int e = 0; e < 16; e++) cvt2(xv[e] * A_SCALE, u0.h[e], u1.h[e]);
        uint32_t o0 = SW128((uint32_t)(cr * 128 + ck0 * 2));
        uint32_t o1 = SW128((uint32_t)(cr * 128 + ck0 * 2 + 16));
        char* base = smem + OFF_A + st * 2 * 8192;
        *(uint4*)(base + o0)            = u0.v[0];
        *(uint4*)(base + o1)            = u0.v[1];
        *(uint4*)(base + 8192 + o0)     = u1.v[0];
        *(uint4*)(base + 8192 + o1)     = u1.v[1];
    };
    auto loadB = [&](int st, int t) {
        const unsigned char* src = g_Wb + (size_t)t * 16384 + tid * 64;
#pragma unroll
        for (int term = 0; term < 2; term++) {
            uint32_t d = sb + OFF_B + (st * 2 + term) * 16384 + tid * 64;
            const unsigned char* s = src + (size_t)term * NCHUNK * 16384;
#pragma unroll
            for (int q = 0; q < 4; q++) cpasync16(d + q * 16, s + q * 16);
        }
    };

    float xv[16];
    {   // prologue
        loadB(0, 0);
        CPCOMMIT();
        loadX(xv, 0);
        storeA(0, xv);
        CPWAIT0();
    }
    __syncthreads();

    for (int t = 0; t < NCHUNK; ++t) {
        const int cur = t & 1, nxt = cur ^ 1;
        const bool hasNext = (t + 1 < NCHUNK);
        if (hasNext) {
            loadB(nxt, t + 1);
            CPCOMMIT();
            loadX(xv, t + 1);
        }
#pragma unroll
        for (int ks = 0; ks < 4; ++ks) {
            uint32_t bfr[2][4][2];
#pragma unroll
            for (int bt = 0; bt < 2; bt++) {
#pragma unroll
                for (int np = 0; np < 2; np++) {
                    uint32_t addr = sb + OFF_B + (cur * 2 + bt) * 16384 +
                        SW128((uint32_t)((ncol + np * 16 + nB) * 128 + (ks * 16 + kB) * 2));
                    ldm_x4(bfr[bt][2 * np][0], bfr[bt][2 * np][1],
                           bfr[bt][2 * np + 1][0], bfr[bt][2 * np + 1][1], addr);
                }
            }
#pragma unroll
            for (int at = 0; at < 2; at++) {
                uint32_t afr[2][4];
#pragma unroll
                for (int mt = 0; mt < 2; mt++) {
                    uint32_t addr = sb + OFF_A + (cur * 2 + at) * 8192 +
                        SW128((uint32_t)((mrow + mt * 16 + rowA) * 128 + (ks * 16 + colA) * 2));
                    ldm_x4(afr[mt][0], afr[mt][1], afr[mt][2], afr[mt][3], addr);
                }
                // products: a0*b0, a0*b1, a1*b0 (drop a1*b1 ~2^-22 rel)
                const int nbt = (at == 0) ? 2 : 1;
                for (int bt = 0; bt < nbt; bt++) {
#pragma unroll
                    for (int mt = 0; mt < 2; mt++)
#pragma unroll
                        for (int nt = 0; nt < 4; nt++)
                            mma_f16(acc[mt][nt], afr[mt], bfr[bt][nt]);
                }
            }
        }
        if (hasNext) {
            storeA(nxt, xv);
            CPWAIT0();
        }
        __syncthreads();
    }

    // ---- epilogue 1: acc*2^-14 + bias -> hbuf ----
    float* hbuf = (float*)(smem + OFF_H);
    {
        int rr = lane >> 2, cc = (lane & 3) * 2;
#pragma unroll
        for (int mt = 0; mt < 2; mt++)
#pragma unroll
            for (int nt = 0; nt < 4; nt++) {
                int r0 = mrow + mt * 16 + rr;
                int c0 = ncol + nt * 8 + cc;
                hbuf[r0 * HSTRIDE + c0]           = acc[mt][nt][0] * UNSCALE + sbias[c0];
                hbuf[r0 * HSTRIDE + c0 + 1]       = acc[mt][nt][1] * UNSCALE + sbias[c0 + 1];
                hbuf[(r0 + 8) * HSTRIDE + c0]     = acc[mt][nt][2] * UNSCALE + sbias[c0];
                hbuf[(r0 + 8) * HSTRIDE + c0 + 1] = acc[mt][nt][3] * UNSCALE + sbias[c0 + 1];
            }
    }
    __syncthreads();

    // ---- epilogue 2: mu (in-place) + kappa ----
    {
        int row = tid >> 2, q = tid & 3;
        float* hrow = &hbuf[row * HSTRIDE + q * 32];
        float nrm = 0.0f, kp = 0.0f;
#pragma unroll
        for (int c = 0; c < 32; c++) {
            float hv = hrow[c];
            nrm = fmaf(hv, hv, nrm);
            kp  = fmaf(hv, swvar[q * 32 + c], kp);
        }
        nrm += __shfl_xor_sync(0xffffffffu, nrm, 1);
        nrm += __shfl_xor_sync(0xffffffffu, nrm, 2);
        kp  += __shfl_xor_sync(0xffffffffu, kp, 1);
        kp  += __shfl_xor_sync(0xffffffffu, kp, 2);
        float rinv = 1.0f / (sqrtf(nrm) + 1e-8f);
#pragma unroll
        for (int c = 0; c < 32; c++) hrow[c] *= rinv;    // hbuf now holds mu
        if (q == 0) {
            float xv2 = kp + bvar[0];
            float sp = fmaxf(xv2, 0.0f) + log1pf(expf(-fabsf(xv2)));
            skap[row] = sp + 1.0f;
        }
    }
    __syncthreads();

    // ---- phase 3: 4-way parallel lazy vMF rejection sampler (4 threads per row) ----
    {
        int row  = tid >> 2, q = tid & 3;
        int grow = rowBase + row;
        K2 root; root.a = 0u; root.b = 42u;
        K2 ke   = keyderive(root, 0u, 0u);
        K2 ku   = keyderive(root, 0u, 1u);
        K2 keyA = keyderive(ke, 0u, 0u);
        K2 keyB = keyderive(ke, 0u, 1u);

        float kap = skap[row];
        float c  = sqrtf(ADDR(MULR(4.0f, MULR(kap, kap)), 16129.0f));
        float bt = DIVR(ADDR(MULR(-2.0f, kap), c), 127.0f);
        float ba = DIVR(127.0f, MULR(4.0f, kap));
        float s  = fminf(fmaxf(SUBR(kap, 10.0f), 0.0f), 1.0f);
        float bb = ADDR(MULR(ba, s), MULR(bt, SUBR(1.0f, s)));
        float aa = DIVR(ADDR(ADDR(127.0f, MULR(2.0f, kap)), c), 4.0f);
        float dd = SUBR(DIVR(MULR(MULR(4.0f, aa), bb), ADDR(1.0f, bb)),
                        MULR(127.0f, (float)4.844187086458591));

        bool done = false;
        float wsel = 0.0f;
        for (int round = 0; round < 16; ++round) {
            if (!__ballot_sync(0xffffffffu, !done)) break;   // warp-uniform early exit
            uint32_t k = (uint32_t)round * 4u + (uint32_t)q;
            float wk = 0.0f;
            uint32_t aflag = 4u;                             // 4 = not accepted
            if (!done) {
                uint32_t i = (uint32_t)grow * 64u + k;
                float e = beta_e(keyderive(keyA, 0u, i), keyderive(keyB, 0u, i));
                float denom = SUBR(1.0f, MULR(SUBR(1.0f, bb), e));
                wk = DIVR(SUBR(1.0f, MULR(ADDR(1.0f, bb), e)), denom);
                float tt = DIVR(MULR(MULR(2.0f, aa), bb), denom);
                float uf = fmaxf(1e-20f, ADDR(u01_from_bits(bits32(ku, 0u, i)), 1e-20f));
                float lhs = ADDR(SUBR(MULR(127.0f, logf(tt)), tt), dd);
                if (lhs > logf(uf)) aflag = (uint32_t)q;
            }
            uint32_t m1 = min(aflag, __shfl_xor_sync(0xffffffffu, aflag, 1));
            uint32_t m2 = min(m1,   __shfl_xor_sync(0xffffffffu, m1, 2));
            int srcq = (m2 < 4u) ? (int)m2 : 3;              // fallback: q=3 holds k=63 on round 15
            float wWin = __shfl_sync(0xffffffffu, wk, (lane & ~3) | srcq);
            if (!done) {
                if (m2 < 4u)            { wsel = wWin; done = true; }
                else if (round == 15)   { wsel = wWin; done = true; }
            }
        }
        if (q == 0) sw[row] = wsel;
    }
    __syncthreads();

    // ---- phase 4: tangent normals + Householder + decoder (warp per row, 8 iters) ----
    K2 root; root.a = 0u; root.b = 42u;
    K2 kv = keyderive(root, 0u, 2u);
    for (int r8 = 0; r8 < 8; r8++) {
        int rloc = r8 * 8 + wid;
        int grow = rowBase + rloc;
        const float* mrowp = &hbuf[rloc * HSTRIDE];
        float mu[4];
#pragma unroll
        for (int q = 0; q < 4; q++) mu[q] = mrowp[lane * 4 + q];

        float v[4];
        float vs = 0.0f;
#pragma unroll
        for (int q = 0; q < 4; q++) {
            int j = lane * 4 + q;
            v[q] = 0.0f;
            if (j >= 1)
                v[q] = normal_from_bits(bits32(kv, 0u, (uint32_t)grow * 127u + (uint32_t)(j - 1)));
            vs = fmaf(v[q], v[q], vs);
        }
        vs = warpAllSum(vs);
        float vninv = 1.0f / sqrtf(vs);

        float w = sw[rloc];
        float wperp = sqrtf(fmaxf(1.0f - w * w, 1e-10f));

        float x[4], uh[4];
        float un = 0.0f;
#pragma unroll
        for (int q = 0; q < 4; q++) {
            int j = lane * 4 + q;
            x[q]  = (j == 0) ? w : wperp * (v[q] * vninv);
            uh[q] = ((j == 0) ? 1.0f : 0.0f) - mu[q];
            un = fmaf(uh[q], uh[q], un);
        }
        un = warpAllSum(un);
        float uinv = 1.0f / (sqrtf(un) + 1e-5f);

        float xd = 0.0f;
#pragma unroll
        for (int q = 0; q < 4; q++) { uh[q] *= uinv; xd = fmaf(x[q], uh[q], xd); }
        xd = warpAllSum(xd);

        float z[4];
#pragma unroll
        for (int q = 0; q < 4; q++) z[q] = x[q] - 2.0f * xd * uh[q];

        float dacc[NCLS];
#pragma unroll
        for (int c = 0; c < NCLS; c++) dacc[c] = 0.0f;
#pragma unroll
        for (int q = 0; q < 4; q++) {
            int r = lane * 4 + q;
#pragma unroll
            for (int c = 0; c < NCLS; c++) dacc[c] = fmaf(z[q], swdec[r * NCLS + c], dacc[c]);
        }
#pragma unroll
        for (int c = 0; c < NCLS; c++) {
            dacc[c] = warpAllSum(dacc[c]);
            if (lane == c) out[grow * NCLS + c] = dacc[c] + bdec[c];
        }
    }
}

extern "C" void kernel_launch(void* const* d_in, const int* in_sizes, int n_in,
                              void* d_out, int out_size) {
    const float* x    = (const float*)d_in[0];
    const float* Wenc = (const float*)d_in[1];
    const float* benc = (const float*)d_in[2];
    const float* Wvar = (const float*)d_in[3];
    const float* bvar = (const float*)d_in[4];
    const float* Wdec = (const float*)d_in[5];
    const float* bdec = (const float*)d_in[6];
    float* out = (float*)d_out;

    cudaFuncSetAttribute(fused_kernel, cudaFuncAttributeMaxDynamicSharedMemorySize, SMEM_ENC);
    convw_kernel<<<(104 * 128 + 255) / 256, 256>>>(Wenc);
    fused_kernel<<<B_ROWS / MTILE, 256, SMEM_ENC>>>(x, benc, Wvar, bvar, Wdec, bdec, out);
}